// round 15
// baseline (speedup 1.0000x reference)
#include <cuda_runtime.h>
#include <cuda_fp16.h>
#include <stdint.h>

#define N_NODES 100000
#define N_FEAT  512
#define N_HID   128
#define N_CLASS 40
#define N_EDGES_MAX 3200000

// ---------------- scratch (device globals; no allocations allowed) ----------
__device__ __half g_xw1h[(size_t)N_NODES * N_HID];   // X @ W1 (fp16)
__device__ __half g_hh [(size_t)N_NODES * N_HID];    // hidden after layer 1 (fp16)
__device__ __half g_hw2h[(size_t)N_NODES * N_CLASS]; // h @ W2 (fp16)
__device__ float  g_w1r[N_FEAT * N_HID];             // W1 pre-rounded to tf32
__device__ int    g_deg[N_NODES];
__device__ int    g_off[N_NODES + 1];
__device__ int    g_rank[N_EDGES_MAX];               // per-edge rank within dst
__device__ int2   g_edge[N_EDGES_MAX];               // dst-sorted {src, w_bits}

// ---------------- streams/events for capture-forked CSR build ---------------
struct ForkCtx {
    cudaStream_t s2;
    cudaEvent_t ev_fork, ev_join;
    ForkCtx() {
        cudaStreamCreateWithFlags(&s2, cudaStreamNonBlocking);
        cudaEventCreateWithFlags(&ev_fork, cudaEventDisableTiming);
        cudaEventCreateWithFlags(&ev_join, cudaEventDisableTiming);
    }
};
static ForkCtx g_fork;

// ---------------- Threefry-2x32-20 -----------------------------------------
__device__ __forceinline__ uint32_t rotl32(uint32_t x, int d) {
    return __funnelshift_l(x, x, d);
}

__device__ __forceinline__ uint2 threefry2x32(uint32_t k0, uint32_t k1,
                                              uint32_t x0, uint32_t x1) {
    uint32_t ks2 = k0 ^ k1 ^ 0x1BD11BDAu;
    x0 += k0; x1 += k1;
#define TF_MIX(r) { x0 += x1; x1 = rotl32(x1, r); x1 ^= x0; }
    TF_MIX(13) TF_MIX(15) TF_MIX(26) TF_MIX(6)   x0 += k1;  x1 += ks2 + 1u;
    TF_MIX(17) TF_MIX(29) TF_MIX(16) TF_MIX(24)  x0 += ks2; x1 += k0 + 2u;
    TF_MIX(13) TF_MIX(15) TF_MIX(26) TF_MIX(6)   x0 += k0;  x1 += k1 + 3u;
    TF_MIX(17) TF_MIX(29) TF_MIX(16) TF_MIX(24)  x0 += k1;  x1 += ks2 + 4u;
    TF_MIX(13) TF_MIX(15) TF_MIX(26) TF_MIX(6)   x0 += ks2; x1 += k0 + 5u;
#undef TF_MIX
    return make_uint2(x0, x1);
}

__device__ __forceinline__ uint32_t f2tf32(float x) {
    uint32_t r;
    asm("cvt.rna.tf32.f32 %0, %1;" : "=r"(r) : "f"(x));
    return r;
}
__device__ __forceinline__ uint32_t u2tf32(uint32_t x) {
    uint32_t r;
    asm("cvt.rna.tf32.f32 %0, %1;" : "=r"(r) : "r"(x));
    return r;
}

// ---------------- cp.async helpers ------------------------------------------
__device__ __forceinline__ void cp_async16(uint32_t daddr, const void* src,
                                           int src_size) {
    asm volatile("cp.async.ca.shared.global [%0], [%1], 16, %2;"
                 :: "r"(daddr), "l"(src), "r"(src_size));
}
#define CP_COMMIT() asm volatile("cp.async.commit_group;")
#define CP_WAIT1()  asm volatile("cp.async.wait_group 1;")
#define CP_WAIT0()  asm volatile("cp.async.wait_group 0;")

// ---------------- ldmatrix helpers ------------------------------------------
__device__ __forceinline__ void ldm_x4(uint32_t& r0, uint32_t& r1,
                                       uint32_t& r2, uint32_t& r3,
                                       uint32_t addr) {
    asm volatile("ldmatrix.sync.aligned.m8n8.x4.shared.b16 {%0,%1,%2,%3}, [%4];"
                 : "=r"(r0), "=r"(r1), "=r"(r2), "=r"(r3) : "r"(addr));
}
__device__ __forceinline__ void ldm_x4_trans(uint32_t& r0, uint32_t& r1,
                                             uint32_t& r2, uint32_t& r3,
                                             uint32_t addr) {
    asm volatile("ldmatrix.sync.aligned.m8n8.x4.trans.shared.b16 {%0,%1,%2,%3}, [%4];"
                 : "=r"(r0), "=r"(r1), "=r"(r2), "=r"(r3) : "r"(addr));
}

// ---------------- W1 pre-round to tf32 --------------------------------------
__global__ __launch_bounds__(256) void w1_round_kernel(
    const float* __restrict__ W1) {
    int i = blockIdx.x * blockDim.x + threadIdx.x;
    if (i < N_FEAT * N_HID)
        ((uint32_t*)g_w1r)[i] = f2tf32(W1[i]);
}

// ---------------- CSR build --------------------------------------------------
__global__ __launch_bounds__(256) void hist_rank_kernel(
    const int* __restrict__ dst, int E) {
    int e = blockIdx.x * blockDim.x + threadIdx.x;
    if (e < E) g_rank[e] = atomicAdd(&g_deg[dst[e]], 1);
}

__global__ __launch_bounds__(1024) void scan_kernel(int n) {
    __shared__ int warp_sums[32];
    int tid = threadIdx.x, lane = tid & 31, wid = tid >> 5;
    int chunk = (n + 1023) / 1024;
    int start = tid * chunk;
    int end = min(start + chunk, n);

    int local = 0;
    for (int i = start; i < end; i++) local += g_deg[i];

    int v = local;
#pragma unroll
    for (int o = 1; o < 32; o <<= 1) {
        int t = __shfl_up_sync(0xffffffffu, v, o);
        if (lane >= o) v += t;
    }
    if (lane == 31) warp_sums[wid] = v;
    __syncthreads();
    if (wid == 0) {
        int s = warp_sums[lane];
#pragma unroll
        for (int o = 1; o < 32; o <<= 1) {
            int t = __shfl_up_sync(0xffffffffu, s, o);
            if (lane >= o) s += t;
        }
        warp_sums[lane] = s;
    }
    __syncthreads();
    int ex = v - local + (wid > 0 ? warp_sums[wid - 1] : 0);

    int run = ex;
    for (int i = start; i < end; i++) {
        g_off[i] = run;
        run += g_deg[i];
    }
    if (tid == 1023) g_off[n] = run;
}

__global__ __launch_bounds__(256) void scatter_kernel(
    const int* __restrict__ src, const int* __restrict__ dst,
    const float* __restrict__ w, int E) {
    int e = blockIdx.x * blockDim.x + threadIdx.x;
    if (e >= E) return;
    int pos = g_off[dst[e]] + g_rank[e];
    g_edge[pos] = make_int2(src[e], __float_as_int(w[e]));
}

// ---------------- GEMM1 (tf32 mma + cp.async double buffer) -----------------
#define G1_AS 36
#define G1_BS 136
__global__ __launch_bounds__(256) void gemm1_tc_kernel(
    const float* __restrict__ A, const float* __restrict__ B,
    __half* __restrict__ C, int M) {
    __shared__ uint32_t As[2][128][G1_AS];
    __shared__ uint32_t Bs[2][32][G1_BS];

    int tid = threadIdx.x, lane = tid & 31, wid = tid >> 5;
    int warp_m = wid & 3, warp_n = wid >> 2;
    int row0 = blockIdx.x * 128;

    float c[2][8][4];
#pragma unroll
    for (int mt = 0; mt < 2; mt++)
#pragma unroll
        for (int nt = 0; nt < 8; nt++)
#pragma unroll
            for (int i = 0; i < 4; i++) c[mt][nt][i] = 0.f;

    auto load_tile = [&](int st, int k0) {
#pragma unroll
        for (int i = 0; i < 4; i++) {
            int f = tid + i * 256;
            int r = f >> 3, c4 = f & 7;
            int gr = row0 + r;
            uint32_t da = (uint32_t)__cvta_generic_to_shared(&As[st][r][c4 * 4]);
            const float* sp = A + (size_t)gr * N_FEAT + k0 + c4 * 4;
            cp_async16(da, sp, (gr < M) ? 16 : 0);
        }
#pragma unroll
        for (int i = 0; i < 4; i++) {
            int f = tid + i * 256;
            int r = f >> 5, c4 = f & 31;
            uint32_t da = (uint32_t)__cvta_generic_to_shared(&Bs[st][r][c4 * 4]);
            const float* sp = B + (size_t)(k0 + r) * N_HID + c4 * 4;
            cp_async16(da, sp, 16);
        }
    };

    load_tile(0, 0);
    CP_COMMIT();

    const int NIT = N_FEAT / 32;  // 16
    for (int it = 0; it < NIT; it++) {
        int st = it & 1;
        if (it + 1 < NIT) {
            load_tile(1 - st, (it + 1) * 32);
            CP_COMMIT();
            CP_WAIT1();
        } else {
            CP_WAIT0();
        }
        __syncthreads();

#pragma unroll
        for (int kk = 0; kk < 4; kk++) {
            uint32_t af[2][4], bf[8][2];
            int colb = kk * 8 + (lane & 3);
#pragma unroll
            for (int mt = 0; mt < 2; mt++) {
                int r = warp_m * 32 + mt * 16 + (lane >> 2);
                af[mt][0] = u2tf32(As[st][r][colb]);
                af[mt][1] = u2tf32(As[st][r + 8][colb]);
                af[mt][2] = u2tf32(As[st][r][colb + 4]);
                af[mt][3] = u2tf32(As[st][r + 8][colb + 4]);
            }
            int rowb = kk * 8 + (lane & 3);
#pragma unroll
            for (int nt = 0; nt < 8; nt++) {
                int cn = warp_n * 64 + nt * 8 + (lane >> 2);
                bf[nt][0] = Bs[st][rowb][cn];
                bf[nt][1] = Bs[st][rowb + 4][cn];
            }
#pragma unroll
            for (int mt = 0; mt < 2; mt++)
#pragma unroll
                for (int nt = 0; nt < 8; nt++) {
                    asm volatile(
                        "mma.sync.aligned.m16n8k8.row.col.f32.tf32.tf32.f32 "
                        "{%0,%1,%2,%3},{%4,%5,%6,%7},{%8,%9},{%0,%1,%2,%3};"
                        : "+f"(c[mt][nt][0]), "+f"(c[mt][nt][1]),
                          "+f"(c[mt][nt][2]), "+f"(c[mt][nt][3])
                        : "r"(af[mt][0]), "r"(af[mt][1]),
                          "r"(af[mt][2]), "r"(af[mt][3]),
                          "r"(bf[nt][0]), "r"(bf[nt][1]));
                }
        }
        __syncthreads();
    }

#pragma unroll
    for (int mt = 0; mt < 2; mt++) {
        int r = row0 + warp_m * 32 + mt * 16 + (lane >> 2);
#pragma unroll
        for (int nt = 0; nt < 8; nt++) {
            int cn = warp_n * 64 + nt * 8 + 2 * (lane & 3);
            if (r < M)
                *(__half2*)(C + (size_t)r * N_HID + cn) =
                    __floats2half2_rn(c[mt][nt][0], c[mt][nt][1]);
            if (r + 8 < M)
                *(__half2*)(C + (size_t)(r + 8) * N_HID + cn) =
                    __floats2half2_rn(c[mt][nt][2], c[mt][nt][3]);
        }
    }
}

// ---------------- SpMM1 CSR (warp/node, fp16 gather, 8x unroll) -------------
__global__ __launch_bounds__(256) void spmm128_csr_kernel(
    const __half* __restrict__ x, const float* __restrict__ b1,
    __half* __restrict__ h, int M) {
    int node = blockIdx.x * 8 + (threadIdx.x >> 5);
    if (node >= M) return;
    int lane = threadIdx.x & 31;
    int beg = g_off[node], end = g_off[node + 1];

    float4 acc = make_float4(0.f, 0.f, 0.f, 0.f);
#define ACC_EDGE(rr, wb) { \
        float ww = __int_as_float(wb); \
        float2 f01 = __half22float2(*(__half2*)&rr.x); \
        float2 f23 = __half22float2(*(__half2*)&rr.y); \
        acc.x += ww * f01.x; acc.y += ww * f01.y; \
        acc.z += ww * f23.x; acc.w += ww * f23.y; }
    int i = beg;
    for (; i + 8 <= end; i += 8) {
        int2 e[8];
        uint2 r[8];
#pragma unroll
        for (int q = 0; q < 8; q++) e[q] = __ldg(&g_edge[i + q]);
#pragma unroll
        for (int q = 0; q < 8; q++)
            r[q] = __ldg((const uint2*)(x + (size_t)e[q].x * N_HID) + lane);
#pragma unroll
        for (int q = 0; q < 8; q++) ACC_EDGE(r[q], e[q].y)
    }
    for (; i < end; i++) {
        int2 e = __ldg(&g_edge[i]);
        uint2 raw = __ldg((const uint2*)(x + (size_t)e.x * N_HID) + lane);
        ACC_EDGE(raw, e.y)
    }
#undef ACC_EDGE
    float4 bv = __ldg((const float4*)b1 + lane);
    float vals[4] = {acc.x + bv.x, acc.y + bv.y, acc.z + bv.z, acc.w + bv.w};
    uint32_t base = (uint32_t)node * N_HID + lane * 4;
#pragma unroll
    for (int j = 0; j < 4; j++) {
        float v = fmaxf(vals[j], 0.f);
        uint2 r = threefry2x32(0u, 42u, 0u, base + j);
        float u = __uint_as_float((r.x >> 9) | 0x3f800000u) - 1.0f;
        vals[j] = (u < 0.5f) ? v * 2.0f : 0.0f;
    }
    uint2 pk;
    *(__half2*)&pk.x = __floats2half2_rn(vals[0], vals[1]);
    *(__half2*)&pk.y = __floats2half2_rn(vals[2], vals[3]);
    *((uint2*)(h + (size_t)node * N_HID) + lane) = pk;
}

// ---------------- GEMM2 (fp16 tensor cores): [M,128]@[128,40] -> fp16 -------
#define G2H_ST 136
#define G2W_ST 56
__global__ __launch_bounds__(256) void gemm2_tc_kernel(
    const __half* __restrict__ H, const float* __restrict__ W2,
    __half* __restrict__ out, int M) {
    __shared__ __half Hs[128 * G2H_ST];
    __shared__ __half Ws[128 * G2W_ST];

    int tid = threadIdx.x, lane = tid & 31, wid = tid >> 5;
    int node0 = blockIdx.x * 128;

    for (int i = tid; i < 128 * 48; i += 256) {
        int k = i / 48, n = i % 48;
        float v = (n < N_CLASS) ? W2[k * N_CLASS + n] : 0.f;
        Ws[k * G2W_ST + n] = __float2half(v);
    }
    for (int i = tid; i < 128 * 16; i += 256) {
        int r = i >> 4, c8 = (i & 15) * 8;
        int gr = node0 + r;
        uint32_t da = (uint32_t)__cvta_generic_to_shared(Hs + r * G2H_ST + c8);
        cp_async16(da, H + (size_t)gr * N_HID + c8, (gr < M) ? 16 : 0);
    }
    CP_COMMIT();
    CP_WAIT0();
    __syncthreads();

    int lr = lane & 7, lm = lane >> 3;

    float c[5][4];
#pragma unroll
    for (int nt = 0; nt < 5; nt++)
#pragma unroll
        for (int i = 0; i < 4; i++) c[nt][i] = 0.f;

#pragma unroll
    for (int k = 0; k < 8; k++) {
        uint32_t a[4];
        {
            int row = wid * 16 + lr + ((lm & 1) << 3);
            int col = k * 16 + ((lm & 2) << 2);
            uint32_t addr = (uint32_t)__cvta_generic_to_shared(
                Hs + row * G2H_ST + col);
            ldm_x4(a[0], a[1], a[2], a[3], addr);
        }
        uint32_t b[6][2];
#pragma unroll
        for (int nt2 = 0; nt2 < 3; nt2++) {
            int krow = k * 16 + lr + ((lm & 1) << 3);
            int coln = nt2 * 16 + ((lm & 2) << 2);
            uint32_t addr = (uint32_t)__cvta_generic_to_shared(
                Ws + krow * G2W_ST + coln);
            ldm_x4_trans(b[2 * nt2][0], b[2 * nt2][1],
                         b[2 * nt2 + 1][0], b[2 * nt2 + 1][1], addr);
        }
#pragma unroll
        for (int nt = 0; nt < 5; nt++) {
            asm volatile(
                "mma.sync.aligned.m16n8k16.row.col.f32.f16.f16.f32 "
                "{%0,%1,%2,%3},{%4,%5,%6,%7},{%8,%9},{%0,%1,%2,%3};"
                : "+f"(c[nt][0]), "+f"(c[nt][1]),
                  "+f"(c[nt][2]), "+f"(c[nt][3])
                : "r"(a[0]), "r"(a[1]), "r"(a[2]), "r"(a[3]),
                  "r"(b[nt][0]), "r"(b[nt][1]));
        }
    }

    int r0 = node0 + wid * 16 + (lane >> 2);
#pragma unroll
    for (int nt = 0; nt < 5; nt++) {
        int cn = nt * 8 + 2 * (lane & 3);
        if (r0 < M)
            *(__half2*)(out + (size_t)r0 * N_CLASS + cn) =
                __floats2half2_rn(c[nt][0], c[nt][1]);
        if (r0 + 8 < M)
            *(__half2*)(out + (size_t)(r0 + 8) * N_CLASS + cn) =
                __floats2half2_rn(c[nt][2], c[nt][3]);
    }
}

// ---------------- fused SpMM2 + bias + log_softmax (warp/node) --------------
// lane l in [0,20): classes {2l, 2l+1}. Edge list loaded once per warp.
__global__ __launch_bounds__(256) void spmm40_lsm_kernel(
    const __half* __restrict__ x, const float* __restrict__ b2,
    float* __restrict__ out, int M) {
    int node = blockIdx.x * 8 + (threadIdx.x >> 5);
    if (node >= M) return;
    int lane = threadIdx.x & 31;
    bool active = lane < 20;
    int cls = lane * 2;              // class pair base (only valid if active)
    int beg = g_off[node], end = g_off[node + 1];

    float a0 = 0.f, a1 = 0.f;
#define ACC2(rw, wb) { \
        float ww = __int_as_float(wb); \
        float2 f = __half22float2(*(__half2*)&rw); \
        a0 += ww * f.x; a1 += ww * f.y; }
    int i = beg;
    for (; i + 4 <= end; i += 4) {
        int2 e0 = __ldg(&g_edge[i + 0]);
        int2 e1 = __ldg(&g_edge[i + 1]);
        int2 e2 = __ldg(&g_edge[i + 2]);
        int2 e3 = __ldg(&g_edge[i + 3]);
        uint32_t r0 = 0, r1 = 0, r2 = 0, r3 = 0;
        if (active) {
            r0 = __ldg((const uint32_t*)(x + (size_t)e0.x * N_CLASS + cls));
            r1 = __ldg((const uint32_t*)(x + (size_t)e1.x * N_CLASS + cls));
            r2 = __ldg((const uint32_t*)(x + (size_t)e2.x * N_CLASS + cls));
            r3 = __ldg((const uint32_t*)(x + (size_t)e3.x * N_CLASS + cls));
        }
        ACC2(r0, e0.y) ACC2(r1, e1.y) ACC2(r2, e2.y) ACC2(r3, e3.y)
    }
    for (; i < end; i++) {
        int2 e = __ldg(&g_edge[i]);
        uint32_t rw = 0;
        if (active)
            rw = __ldg((const uint32_t*)(x + (size_t)e.x * N_CLASS + cls));
        ACC2(rw, e.y)
    }
#undef ACC2

    float v0 = -3.402823466e38f, v1 = -3.402823466e38f;
    if (active) {
        float2 bb = __ldg((const float2*)b2 + lane);
        v0 = a0 + bb.x;
        v1 = a1 + bb.y;
    }
    float m = fmaxf(v0, v1);
#pragma unroll
    for (int o = 16; o > 0; o >>= 1)
        m = fmaxf(m, __shfl_xor_sync(0xffffffffu, m, o));
    float s = active ? (expf(v0 - m) + expf(v1 - m)) : 0.f;
#pragma unroll
    for (int o = 16; o > 0; o >>= 1)
        s += __shfl_xor_sync(0xffffffffu, s, o);
    float lse = m + logf(s);
    if (active)
        *((float2*)(out + (size_t)node * N_CLASS) + lane) =
            make_float2(v0 - lse, v1 - lse);
}

// ---------------- launcher ---------------------------------------------------
extern "C" void kernel_launch(void* const* d_in, const int* in_sizes, int n_in,
                              void* d_out, int out_size) {
    const float* feature = (const float*)d_in[0];
    const int*   esrc    = (const int*)d_in[1];
    const int*   edst    = (const int*)d_in[2];
    const float* ew      = (const float*)d_in[3];
    const float* W1      = (const float*)d_in[4];
    const float* b1      = (const float*)d_in[5];
    const float* W2      = (const float*)d_in[6];
    const float* b2      = (const float*)d_in[7];
    float* out = (float*)d_out;

    int M = in_sizes[0] / N_FEAT;   // 100000
    int E = in_sizes[1];            // 3200000

    __half *xw1h, *hh, *hw2h;
    float *w1r;
    int *deg;
    cudaGetSymbolAddress((void**)&xw1h, g_xw1h);
    cudaGetSymbolAddress((void**)&hh,   g_hh);
    cudaGetSymbolAddress((void**)&hw2h, g_hw2h);
    cudaGetSymbolAddress((void**)&w1r,  g_w1r);
    cudaGetSymbolAddress((void**)&deg,  g_deg);

    cudaStream_t s0 = 0;
    cudaStream_t s2 = g_fork.s2;

    // fork: CSR build on s2, concurrent with gemm1 chain on s0
    cudaEventRecord(g_fork.ev_fork, s0);
    cudaStreamWaitEvent(s2, g_fork.ev_fork, 0);

    cudaMemsetAsync(deg, 0, sizeof(int) * N_NODES, s2);
    hist_rank_kernel<<<(E + 255) / 256, 256, 0, s2>>>(edst, E);
    scan_kernel<<<1, 1024, 0, s2>>>(M);
    scatter_kernel<<<(E + 255) / 256, 256, 0, s2>>>(esrc, edst, ew, E);
    cudaEventRecord(g_fork.ev_join, s2);

    // main chain
    w1_round_kernel<<<(N_FEAT * N_HID + 255) / 256, 256, 0, s0>>>(W1);
    gemm1_tc_kernel<<<(M + 127) / 128, 256, 0, s0>>>(feature, w1r, xw1h, M);

    // join: spmm needs both gemm1 and CSR
    cudaStreamWaitEvent(s0, g_fork.ev_join, 0);
    spmm128_csr_kernel<<<(M + 7) / 8, 256, 0, s0>>>(xw1h, b1, hh, M);

    // layer 2
    gemm2_tc_kernel<<<(M + 127) / 128, 256, 0, s0>>>(hh, W2, hw2h, M);
    spmm40_lsm_kernel<<<(M + 7) / 8, 256, 0, s0>>>(hw2h, b2, out, M);
}

// round 17
// speedup vs baseline: 1.4055x; 1.4055x over previous
#include <cuda_runtime.h>
#include <cuda_fp16.h>
#include <stdint.h>

#define N_NODES 100000
#define N_FEAT  512
#define N_HID   128
#define N_CLASS 40
#define N_EDGES_MAX 3200000
#define SCAN_BLK 256

// ---------------- scratch (device globals; no allocations allowed) ----------
__device__ __half g_xw1h[(size_t)N_NODES * N_HID];   // X @ W1 (fp16)
__device__ __half g_hh [(size_t)N_NODES * N_HID];    // hidden after layer 1 (fp16)
__device__ __half g_hw2h[(size_t)N_NODES * N_CLASS]; // h @ W2 (fp16)
__device__ int    g_deg[N_NODES];
__device__ int    g_off[N_NODES + 1];
__device__ int    g_rank[N_EDGES_MAX];               // per-edge rank within dst
__device__ int2   g_edge[N_EDGES_MAX];               // dst-sorted {src, w_bits}
__device__ int    g_bsum[(N_NODES + SCAN_BLK - 1) / SCAN_BLK + 1];

// ---------------- streams/events for capture-forked CSR build ---------------
struct ForkCtx {
    cudaStream_t s2;
    cudaEvent_t ev_fork, ev_join;
    ForkCtx() {
        cudaStreamCreateWithFlags(&s2, cudaStreamNonBlocking);
        cudaEventCreateWithFlags(&ev_fork, cudaEventDisableTiming);
        cudaEventCreateWithFlags(&ev_join, cudaEventDisableTiming);
    }
};
static ForkCtx g_fork;

// ---------------- Threefry-2x32-20 -----------------------------------------
__device__ __forceinline__ uint32_t rotl32(uint32_t x, int d) {
    return __funnelshift_l(x, x, d);
}

__device__ __forceinline__ uint2 threefry2x32(uint32_t k0, uint32_t k1,
                                              uint32_t x0, uint32_t x1) {
    uint32_t ks2 = k0 ^ k1 ^ 0x1BD11BDAu;
    x0 += k0; x1 += k1;
#define TF_MIX(r) { x0 += x1; x1 = rotl32(x1, r); x1 ^= x0; }
    TF_MIX(13) TF_MIX(15) TF_MIX(26) TF_MIX(6)   x0 += k1;  x1 += ks2 + 1u;
    TF_MIX(17) TF_MIX(29) TF_MIX(16) TF_MIX(24)  x0 += ks2; x1 += k0 + 2u;
    TF_MIX(13) TF_MIX(15) TF_MIX(26) TF_MIX(6)   x0 += k0;  x1 += k1 + 3u;
    TF_MIX(17) TF_MIX(29) TF_MIX(16) TF_MIX(24)  x0 += k1;  x1 += ks2 + 4u;
    TF_MIX(13) TF_MIX(15) TF_MIX(26) TF_MIX(6)   x0 += ks2; x1 += k0 + 5u;
#undef TF_MIX
    return make_uint2(x0, x1);
}

__device__ __forceinline__ uint32_t u2tf32(uint32_t x) {
    uint32_t r;
    asm("cvt.rna.tf32.f32 %0, %1;" : "=r"(r) : "r"(x));
    return r;
}

// ---------------- cp.async helpers ------------------------------------------
__device__ __forceinline__ void cp_async16(uint32_t daddr, const void* src,
                                           int src_size) {
    asm volatile("cp.async.ca.shared.global [%0], [%1], 16, %2;"
                 :: "r"(daddr), "l"(src), "r"(src_size));
}
#define CP_COMMIT() asm volatile("cp.async.commit_group;")
#define CP_WAIT1()  asm volatile("cp.async.wait_group 1;")
#define CP_WAIT0()  asm volatile("cp.async.wait_group 0;")

// ---------------- ldmatrix helpers ------------------------------------------
__device__ __forceinline__ void ldm_x4(uint32_t& r0, uint32_t& r1,
                                       uint32_t& r2, uint32_t& r3,
                                       uint32_t addr) {
    asm volatile("ldmatrix.sync.aligned.m8n8.x4.shared.b16 {%0,%1,%2,%3}, [%4];"
                 : "=r"(r0), "=r"(r1), "=r"(r2), "=r"(r3) : "r"(addr));
}
__device__ __forceinline__ void ldm_x4_trans(uint32_t& r0, uint32_t& r1,
                                             uint32_t& r2, uint32_t& r3,
                                             uint32_t addr) {
    asm volatile("ldmatrix.sync.aligned.m8n8.x4.trans.shared.b16 {%0,%1,%2,%3}, [%4];"
                 : "=r"(r0), "=r"(r1), "=r"(r2), "=r"(r3) : "r"(addr));
}

// ---------------- CSR build --------------------------------------------------
__global__ __launch_bounds__(256) void hist_rank_kernel(
    const int* __restrict__ dst, int E) {
    int e = blockIdx.x * blockDim.x + threadIdx.x;
    if (e < E) g_rank[e] = atomicAdd(&g_deg[dst[e]], 1);
}

// phase 1: per-block sums (coalesced)
__global__ __launch_bounds__(SCAN_BLK) void scan1_kernel(int n) {
    __shared__ int ws[SCAN_BLK / 32];
    int i = blockIdx.x * SCAN_BLK + threadIdx.x;
    int v = (i < n) ? g_deg[i] : 0;
    int lane = threadIdx.x & 31, wid = threadIdx.x >> 5;
#pragma unroll
    for (int o = 16; o > 0; o >>= 1) v += __shfl_down_sync(0xffffffffu, v, o);
    if (lane == 0) ws[wid] = v;
    __syncthreads();
    if (threadIdx.x == 0) {
        int s = 0;
#pragma unroll
        for (int w = 0; w < SCAN_BLK / 32; w++) s += ws[w];
        g_bsum[blockIdx.x] = s;
    }
}

// phase 2: single-block exclusive scan of block sums (nb <= 1024)
// all shfl ops executed by ALL lanes (inactive carry 0)
__global__ __launch_bounds__(1024) void scan2_kernel(int nb) {
    __shared__ int ws[32];
    int tid = threadIdx.x, lane = tid & 31, wid = tid >> 5;
    int v = (tid < nb) ? g_bsum[tid] : 0;
    int inc = v;
#pragma unroll
    for (int o = 1; o < 32; o <<= 1) {
        int t = __shfl_up_sync(0xffffffffu, inc, o);
        if (lane >= o) inc += t;
    }
    if (lane == 31) ws[wid] = inc;
    __syncthreads();
    if (wid == 0) {
        int s = ws[lane];
#pragma unroll
        for (int o = 1; o < 32; o <<= 1) {
            int t = __shfl_up_sync(0xffffffffu, s, o);
            if (lane >= o) s += t;
        }
        ws[lane] = s;
    }
    __syncthreads();
    int ex = inc - v + (wid > 0 ? ws[wid - 1] : 0);
    if (tid < nb) g_bsum[tid] = ex;
}

// phase 3: block-local exclusive scan + base, write offsets (coalesced)
// FIX vs R16: warp-0 combine executes shfl with ALL 32 lanes (no partial-mask UB)
__global__ __launch_bounds__(SCAN_BLK) void scan3_kernel(int n, int E) {
    __shared__ int ws[SCAN_BLK / 32];
    int i = blockIdx.x * SCAN_BLK + threadIdx.x;
    int v = (i < n) ? g_deg[i] : 0;
    int lane = threadIdx.x & 31, wid = threadIdx.x >> 5;
    int inc = v;
#pragma unroll
    for (int o = 1; o < 32; o <<= 1) {
        int t = __shfl_up_sync(0xffffffffu, inc, o);
        if (lane >= o) inc += t;
    }
    if (lane == 31) ws[wid] = inc;
    __syncthreads();
    if (wid == 0) {
        int s = (lane < SCAN_BLK / 32) ? ws[lane] : 0;
#pragma unroll
        for (int o = 1; o < 32; o <<= 1) {
            int t = __shfl_up_sync(0xffffffffu, s, o);
            if (lane >= o) s += t;
        }
        if (lane < SCAN_BLK / 32) ws[lane] = s;
    }
    __syncthreads();
    int ex = inc - v + (wid > 0 ? ws[wid - 1] : 0) + g_bsum[blockIdx.x];
    if (i < n) g_off[i] = ex;
    if (i == n - 1) g_off[n] = E;
}

__global__ __launch_bounds__(256) void scatter_kernel(
    const int* __restrict__ src, const int* __restrict__ dst,
    const float* __restrict__ w, int E) {
    int e = blockIdx.x * blockDim.x + threadIdx.x;
    if (e >= E) return;
    int pos = g_off[dst[e]] + g_rank[e];
    g_edge[pos] = make_int2(src[e], __float_as_int(w[e]));
}

// ---------------- GEMM1 (tf32 mma + cp.async double buffer) -----------------
// in-register cvt.rna for BOTH operands (no pre-round pass)
#define G1_AS 36
#define G1_BS 136
__global__ __launch_bounds__(256) void gemm1_tc_kernel(
    const float* __restrict__ A, const float* __restrict__ B,
    __half* __restrict__ C, int M) {
    __shared__ uint32_t As[2][128][G1_AS];
    __shared__ uint32_t Bs[2][32][G1_BS];

    int tid = threadIdx.x, lane = tid & 31, wid = tid >> 5;
    int warp_m = wid & 3, warp_n = wid >> 2;
    int row0 = blockIdx.x * 128;

    float c[2][8][4];
#pragma unroll
    for (int mt = 0; mt < 2; mt++)
#pragma unroll
        for (int nt = 0; nt < 8; nt++)
#pragma unroll
            for (int i = 0; i < 4; i++) c[mt][nt][i] = 0.f;

    auto load_tile = [&](int st, int k0) {
#pragma unroll
        for (int i = 0; i < 4; i++) {
            int f = tid + i * 256;
            int r = f >> 3, c4 = f & 7;
            int gr = row0 + r;
            uint32_t da = (uint32_t)__cvta_generic_to_shared(&As[st][r][c4 * 4]);
            const float* sp = A + (size_t)gr * N_FEAT + k0 + c4 * 4;
            cp_async16(da, sp, (gr < M) ? 16 : 0);
        }
#pragma unroll
        for (int i = 0; i < 4; i++) {
            int f = tid + i * 256;
            int r = f >> 5, c4 = f & 31;
            uint32_t da = (uint32_t)__cvta_generic_to_shared(&Bs[st][r][c4 * 4]);
            const float* sp = B + (size_t)(k0 + r) * N_HID + c4 * 4;
            cp_async16(da, sp, 16);
        }
    };

    load_tile(0, 0);
    CP_COMMIT();

    const int NIT = N_FEAT / 32;  // 16
    for (int it = 0; it < NIT; it++) {
        int st = it & 1;
        if (it + 1 < NIT) {
            load_tile(1 - st, (it + 1) * 32);
            CP_COMMIT();
            CP_WAIT1();
        } else {
            CP_WAIT0();
        }
        __syncthreads();

#pragma unroll
        for (int kk = 0; kk < 4; kk++) {
            uint32_t af[2][4], bf[8][2];
            int colb = kk * 8 + (lane & 3);
#pragma unroll
            for (int mt = 0; mt < 2; mt++) {
                int r = warp_m * 32 + mt * 16 + (lane >> 2);
                af[mt][0] = u2tf32(As[st][r][colb]);
                af[mt][1] = u2tf32(As[st][r + 8][colb]);
                af[mt][2] = u2tf32(As[st][r][colb + 4]);
                af[mt][3] = u2tf32(As[st][r + 8][colb + 4]);
            }
            int rowb = kk * 8 + (lane & 3);
#pragma unroll
            for (int nt = 0; nt < 8; nt++) {
                int cn = warp_n * 64 + nt * 8 + (lane >> 2);
                bf[nt][0] = u2tf32(Bs[st][rowb][cn]);
                bf[nt][1] = u2tf32(Bs[st][rowb + 4][cn]);
            }
#pragma unroll
            for (int mt = 0; mt < 2; mt++)
#pragma unroll
                for (int nt = 0; nt < 8; nt++) {
                    asm volatile(
                        "mma.sync.aligned.m16n8k8.row.col.f32.tf32.tf32.f32 "
                        "{%0,%1,%2,%3},{%4,%5,%6,%7},{%8,%9},{%0,%1,%2,%3};"
                        : "+f"(c[mt][nt][0]), "+f"(c[mt][nt][1]),
                          "+f"(c[mt][nt][2]), "+f"(c[mt][nt][3])
                        : "r"(af[mt][0]), "r"(af[mt][1]),
                          "r"(af[mt][2]), "r"(af[mt][3]),
                          "r"(bf[nt][0]), "r"(bf[nt][1]));
                }
        }
        __syncthreads();
    }

#pragma unroll
    for (int mt = 0; mt < 2; mt++) {
        int r = row0 + warp_m * 32 + mt * 16 + (lane >> 2);
#pragma unroll
        for (int nt = 0; nt < 8; nt++) {
            int cn = warp_n * 64 + nt * 8 + 2 * (lane & 3);
            if (r < M)
                *(__half2*)(C + (size_t)r * N_HID + cn) =
                    __floats2half2_rn(c[mt][nt][0], c[mt][nt][1]);
            if (r + 8 < M)
                *(__half2*)(C + (size_t)(r + 8) * N_HID + cn) =
                    __floats2half2_rn(c[mt][nt][2], c[mt][nt][3]);
        }
    }
}

// ---------------- SpMM1 CSR (warp/node, fp16 gather, 8x unroll) -------------
__global__ __launch_bounds__(256) void spmm128_csr_kernel(
    const __half* __restrict__ x, const float* __restrict__ b1,
    __half* __restrict__ h, int M) {
    int node = blockIdx.x * 8 + (threadIdx.x >> 5);
    if (node >= M) return;
    int lane = threadIdx.x & 31;
    int beg = g_off[node], end = g_off[node + 1];

    float4 acc = make_float4(0.f, 0.f, 0.f, 0.f);
#define ACC_EDGE(rr, wb) { \
        float ww = __int_as_float(wb); \
        float2 f01 = __half22float2(*(__half2*)&rr.x); \
        float2 f23 = __half22float2(*(__half2*)&rr.y); \
        acc.x += ww * f01.x; acc.y += ww * f01.y; \
        acc.z += ww * f23.x; acc.w += ww * f23.y; }
    int i = beg;
    for (; i + 8 <= end; i += 8) {
        int2 e[8];
        uint2 r[8];
#pragma unroll
        for (int q = 0; q < 8; q++) e[q] = __ldg(&g_edge[i + q]);
#pragma unroll
        for (int q = 0; q < 8; q++)
            r[q] = __ldg((const uint2*)(x + (size_t)e[q].x * N_HID) + lane);
#pragma unroll
        for (int q = 0; q < 8; q++) ACC_EDGE(r[q], e[q].y)
    }
    for (; i < end; i++) {
        int2 e = __ldg(&g_edge[i]);
        uint2 raw = __ldg((const uint2*)(x + (size_t)e.x * N_HID) + lane);
        ACC_EDGE(raw, e.y)
    }
#undef ACC_EDGE
    float4 bv = __ldg((const float4*)b1 + lane);
    float vals[4] = {acc.x + bv.x, acc.y + bv.y, acc.z + bv.z, acc.w + bv.w};
    uint32_t base = (uint32_t)node * N_HID + lane * 4;
#pragma unroll
    for (int j = 0; j < 4; j++) {
        float v = fmaxf(vals[j], 0.f);
        uint2 r = threefry2x32(0u, 42u, 0u, base + j);
        float u = __uint_as_float((r.x >> 9) | 0x3f800000u) - 1.0f;
        vals[j] = (u < 0.5f) ? v * 2.0f : 0.0f;
    }
    uint2 pk;
    *(__half2*)&pk.x = __floats2half2_rn(vals[0], vals[1]);
    *(__half2*)&pk.y = __floats2half2_rn(vals[2], vals[3]);
    *((uint2*)(h + (size_t)node * N_HID) + lane) = pk;
}

// ---------------- GEMM2 (fp16 tensor cores): [M,128]@[128,40] -> fp16 -------
#define G2H_ST 136
#define G2W_ST 56
__global__ __launch_bounds__(256) void gemm2_tc_kernel(
    const __half* __restrict__ H, const float* __restrict__ W2,
    __half* __restrict__ out, int M) {
    __shared__ __half Hs[128 * G2H_ST];
    __shared__ __half Ws[128 * G2W_ST];

    int tid = threadIdx.x, lane = tid & 31, wid = tid >> 5;
    int node0 = blockIdx.x * 128;

    for (int i = tid; i < 128 * 48; i += 256) {
        int k = i / 48, n = i % 48;
        float v = (n < N_CLASS) ? W2[k * N_CLASS + n] : 0.f;
        Ws[k * G2W_ST + n] = __float2half(v);
    }
    for (int i = tid; i < 128 * 16; i += 256) {
        int r = i >> 4, c8 = (i & 15) * 8;
        int gr = node0 + r;
        uint32_t da = (uint32_t)__cvta_generic_to_shared(Hs + r * G2H_ST + c8);
        cp_async16(da, H + (size_t)gr * N_HID + c8, (gr < M) ? 16 : 0);
    }
    CP_COMMIT();
    CP_WAIT0();
    __syncthreads();

    int lr = lane & 7, lm = lane >> 3;

    float c[5][4];
#pragma unroll
    for (int nt = 0; nt < 5; nt++)
#pragma unroll
        for (int i = 0; i < 4; i++) c[nt][i] = 0.f;

#pragma unroll
    for (int k = 0; k < 8; k++) {
        uint32_t a[4];
        {
            int row = wid * 16 + lr + ((lm & 1) << 3);
            int col = k * 16 + ((lm & 2) << 2);
            uint32_t addr = (uint32_t)__cvta_generic_to_shared(
                Hs + row * G2H_ST + col);
            ldm_x4(a[0], a[1], a[2], a[3], addr);
        }
        uint32_t b[6][2];
#pragma unroll
        for (int nt2 = 0; nt2 < 3; nt2++) {
            int krow = k * 16 + lr + ((lm & 1) << 3);
            int coln = nt2 * 16 + ((lm & 2) << 2);
            uint32_t addr = (uint32_t)__cvta_generic_to_shared(
                Ws + krow * G2W_ST + coln);
            ldm_x4_trans(b[2 * nt2][0], b[2 * nt2][1],
                         b[2 * nt2 + 1][0], b[2 * nt2 + 1][1], addr);
        }
#pragma unroll
        for (int nt = 0; nt < 5; nt++) {
            asm volatile(
                "mma.sync.aligned.m16n8k16.row.col.f32.f16.f16.f32 "
                "{%0,%1,%2,%3},{%4,%5,%6,%7},{%8,%9},{%0,%1,%2,%3};"
                : "+f"(c[nt][0]), "+f"(c[nt][1]),
                  "+f"(c[nt][2]), "+f"(c[nt][3])
                : "r"(a[0]), "r"(a[1]), "r"(a[2]), "r"(a[3]),
                  "r"(b[nt][0]), "r"(b[nt][1]));
        }
    }

    int r0 = node0 + wid * 16 + (lane >> 2);
#pragma unroll
    for (int nt = 0; nt < 5; nt++) {
        int cn = nt * 8 + 2 * (lane & 3);
        if (r0 < M)
            *(__half2*)(out + (size_t)r0 * N_CLASS + cn) =
                __floats2half2_rn(c[nt][0], c[nt][1]);
        if (r0 + 8 < M)
            *(__half2*)(out + (size_t)(r0 + 8) * N_CLASS + cn) =
                __floats2half2_rn(c[nt][2], c[nt][3]);
    }
}

// ---------------- fused SpMM2 + bias + log_softmax (warp/node) --------------
__global__ __launch_bounds__(256) void spmm40_lsm_kernel(
    const __half* __restrict__ x, const float* __restrict__ b2,
    float* __restrict__ out, int M) {
    int node = blockIdx.x * 8 + (threadIdx.x >> 5);
    if (node >= M) return;
    int lane = threadIdx.x & 31;
    bool active = lane < 20;
    int cls = lane * 2;
    int beg = g_off[node], end = g_off[node + 1];

    float a0 = 0.f, a1 = 0.f;
#define ACC2(rw, wb) { \
        float ww = __int_as_float(wb); \
        float2 f = __half22float2(*(__half2*)&rw); \
        a0 += ww * f.x; a1 += ww * f.y; }
    int i = beg;
    for (; i + 4 <= end; i += 4) {
        int2 e0 = __ldg(&g_edge[i + 0]);
        int2 e1 = __ldg(&g_edge[i + 1]);
        int2 e2 = __ldg(&g_edge[i + 2]);
        int2 e3 = __ldg(&g_edge[i + 3]);
        uint32_t r0 = 0, r1 = 0, r2 = 0, r3 = 0;
        if (active) {
            r0 = __ldg((const uint32_t*)(x + (size_t)e0.x * N_CLASS + cls));
            r1 = __ldg((const uint32_t*)(x + (size_t)e1.x * N_CLASS + cls));
            r2 = __ldg((const uint32_t*)(x + (size_t)e2.x * N_CLASS + cls));
            r3 = __ldg((const uint32_t*)(x + (size_t)e3.x * N_CLASS + cls));
        }
        ACC2(r0, e0.y) ACC2(r1, e1.y) ACC2(r2, e2.y) ACC2(r3, e3.y)
    }
    for (; i < end; i++) {
        int2 e = __ldg(&g_edge[i]);
        uint32_t rw = 0;
        if (active)
            rw = __ldg((const uint32_t*)(x + (size_t)e.x * N_CLASS + cls));
        ACC2(rw, e.y)
    }
#undef ACC2

    float v0 = -3.402823466e38f, v1 = -3.402823466e38f;
    if (active) {
        float2 bb = __ldg((const float2*)b2 + lane);
        v0 = a0 + bb.x;
        v1 = a1 + bb.y;
    }
    float m = fmaxf(v0, v1);
#pragma unroll
    for (int o = 16; o > 0; o >>= 1)
        m = fmaxf(m, __shfl_xor_sync(0xffffffffu, m, o));
    float s = active ? (expf(v0 - m) + expf(v1 - m)) : 0.f;
#pragma unroll
    for (int o = 16; o > 0; o >>= 1)
        s += __shfl_xor_sync(0xffffffffu, s, o);
    float lse = m + logf(s);
    if (active)
        *((float2*)(out + (size_t)node * N_CLASS) + lane) =
            make_float2(v0 - lse, v1 - lse);
}

// ---------------- launcher ---------------------------------------------------
extern "C" void kernel_launch(void* const* d_in, const int* in_sizes, int n_in,
                              void* d_out, int out_size) {
    const float* feature = (const float*)d_in[0];
    const int*   esrc    = (const int*)d_in[1];
    const int*   edst    = (const int*)d_in[2];
    const float* ew      = (const float*)d_in[3];
    const float* W1      = (const float*)d_in[4];
    const float* b1      = (const float*)d_in[5];
    const float* W2      = (const float*)d_in[6];
    const float* b2      = (const float*)d_in[7];
    float* out = (float*)d_out;

    int M = in_sizes[0] / N_FEAT;   // 100000
    int E = in_sizes[1];            // 3200000

    __half *xw1h, *hh, *hw2h;
    int *deg;
    cudaGetSymbolAddress((void**)&xw1h, g_xw1h);
    cudaGetSymbolAddress((void**)&hh,   g_hh);
    cudaGetSymbolAddress((void**)&hw2h, g_hw2h);
    cudaGetSymbolAddress((void**)&deg,  g_deg);

    cudaStream_t s0 = 0;
    cudaStream_t s2 = g_fork.s2;

    int nb = (M + SCAN_BLK - 1) / SCAN_BLK;   // 391 blocks

    // fork: CSR build on s2, concurrent with gemm1 on s0
    cudaEventRecord(g_fork.ev_fork, s0);
    cudaStreamWaitEvent(s2, g_fork.ev_fork, 0);

    cudaMemsetAsync(deg, 0, sizeof(int) * N_NODES, s2);
    hist_rank_kernel<<<(E + 255) / 256, 256, 0, s2>>>(edst, E);
    scan1_kernel<<<nb, SCAN_BLK, 0, s2>>>(M);
    scan2_kernel<<<1, 1024, 0, s2>>>(nb);
    scan3_kernel<<<nb, SCAN_BLK, 0, s2>>>(M, E);
    scatter_kernel<<<(E + 255) / 256, 256, 0, s2>>>(esrc, edst, ew, E);
    cudaEventRecord(g_fork.ev_join, s2);

    // main chain
    gemm1_tc_kernel<<<(M + 127) / 128, 256, 0, s0>>>(feature, W1, xw1h, M);

    // join: spmm needs both gemm1 and CSR
    cudaStreamWaitEvent(s0, g_fork.ev_join, 0);
    spmm128_csr_kernel<<<(M + 7) / 8, 256, 0, s0>>>(xw1h, b1, hh, M);

    // layer 2
    gemm2_tc_kernel<<<(M + 127) / 128, 256, 0, s0>>>(hh, W2, hw2h, M);
    spmm40_lsm_kernel<<<(M + 7) / 8, 256, 0, s0>>>(hw2h, b2, out, M);
}